// round 4
// baseline (speedup 1.0000x reference)
#include <cuda_runtime.h>
#include <cuda_bf16.h>
#include <cstdint>

// Skip-gram negative-sampling loss, fused:
//   loss = -(1/N) * sum_n [ logsig(dot(t_n, c_n)) + logsig(-dot(sum_k e_nk, t_n)) ]
//
// Inputs (metadata order):
//   d_in[0]: targets_1_pos          int32 [N]
//   d_in[1]: contexts_1_pos         int32 [N]
//   d_in[2]: contexts_0_pos_samples int32 [N, K]
//   d_in[3]: W_hidden               float32 [V, D]
//   d_in[4]: W_output               float32 [V, D]
// Output: float32 scalar.
//
// R4 == R2/R3 design resubmit (both benches were broker-side infra failures;
// the kernel never executed). Changes vs the R1 147.8us baseline:
//  - init kernel removed: per-block partials written by OVERWRITE into a
//    __device__ array (deterministic, no zeroing needed), finalize reduces.
//  - grid resized to exactly one wave: 148 SMs * 8 blocks = 1184 blocks.
//  - main loop processes 2 pairs per warp iteration (14 independent row
//    gathers in flight before the shuffle-reduce dependency).
//  - finalize simplified to a warp-shuffle reduction (fewer syncs).

#define K_NEG 5
#define NBLOCKS 1184          // 148 SMs * 8 blocks -> one wave @ 256 thr
#define NTHREADS 256
#define WARPS_PER_BLOCK (NTHREADS / 32)

__device__ float g_partials[NBLOCKS];

__device__ __forceinline__ float log_sigmoid(float x) {
    // stable: min(x,0) - log1p(exp(-|x|))
    return fminf(x, 0.0f) - log1pf(expf(-fabsf(x)));
}

// one pair's gather + partial dots for this lane
struct PairAcc {
    float pos;     // lane-partial of dot(t, c)
    float negdot;  // lane-partial of dot(t, sum_k e_k)
};

__device__ __forceinline__ PairAcc do_pair(const int* __restrict__ tgt,
                                           const int* __restrict__ ctx,
                                           const int* __restrict__ neg,
                                           const float4* __restrict__ Wh,
                                           const float4* __restrict__ Wo,
                                           long long p, int lane) {
    const size_t ti = (size_t)tgt[p];
    const size_t ci = (size_t)ctx[p];

    const float4 t = Wh[ti * 32 + lane];
    const float4 c = Wo[ci * 32 + lane];

    float4 s = make_float4(0.f, 0.f, 0.f, 0.f);
    const int* ng = neg + p * K_NEG;
#pragma unroll
    for (int k = 0; k < K_NEG; k++) {
        const float4 e = Wo[(size_t)ng[k] * 32 + lane];
        s.x += e.x; s.y += e.y; s.z += e.z; s.w += e.w;
    }

    PairAcc a;
    a.pos    = t.x * c.x + t.y * c.y + t.z * c.z + t.w * c.w;
    a.negdot = s.x * t.x + s.y * t.y + s.z * t.z + s.w * t.w;
    return a;
}

__global__ __launch_bounds__(NTHREADS)
void sg_main_kernel(const int* __restrict__ tgt,
                    const int* __restrict__ ctx,
                    const int* __restrict__ neg,
                    const float4* __restrict__ Wh,   // [V, 32] float4 rows
                    const float4* __restrict__ Wo,   // [V, 32] float4 rows
                    long long n) {
    const int lane = threadIdx.x & 31;
    const int warp_in_block = threadIdx.x >> 5;
    const long long warp_global = (long long)blockIdx.x * WARPS_PER_BLOCK + warp_in_block;
    const long long warp_stride = (long long)gridDim.x * WARPS_PER_BLOCK;

    float local_sum = 0.0f;

    long long p = warp_global;
    // 2 pairs per iteration: 14 independent row gathers in flight
    for (; p + warp_stride < n; p += 2 * warp_stride) {
        PairAcc a0 = do_pair(tgt, ctx, neg, Wh, Wo, p, lane);
        PairAcc a1 = do_pair(tgt, ctx, neg, Wh, Wo, p + warp_stride, lane);

#pragma unroll
        for (int off = 16; off > 0; off >>= 1) {
            a0.pos    += __shfl_xor_sync(0xFFFFFFFFu, a0.pos, off);
            a0.negdot += __shfl_xor_sync(0xFFFFFFFFu, a0.negdot, off);
            a1.pos    += __shfl_xor_sync(0xFFFFFFFFu, a1.pos, off);
            a1.negdot += __shfl_xor_sync(0xFFFFFFFFu, a1.negdot, off);
        }
        if (lane == 0) {
            local_sum += log_sigmoid(a0.pos) + log_sigmoid(-a0.negdot)
                       + log_sigmoid(a1.pos) + log_sigmoid(-a1.negdot);
        }
    }
    // tail: at most one pair left for this warp
    if (p < n) {
        PairAcc a0 = do_pair(tgt, ctx, neg, Wh, Wo, p, lane);
#pragma unroll
        for (int off = 16; off > 0; off >>= 1) {
            a0.pos    += __shfl_xor_sync(0xFFFFFFFFu, a0.pos, off);
            a0.negdot += __shfl_xor_sync(0xFFFFFFFFu, a0.negdot, off);
        }
        if (lane == 0)
            local_sum += log_sigmoid(a0.pos) + log_sigmoid(-a0.negdot);
    }

    // block reduce -> overwrite this block's partial (no init kernel needed)
    __shared__ float warp_sums[WARPS_PER_BLOCK];
    if (lane == 0) warp_sums[warp_in_block] = local_sum;
    __syncthreads();

    if (warp_in_block == 0) {
        float v = (lane < WARPS_PER_BLOCK) ? warp_sums[lane] : 0.0f;
#pragma unroll
        for (int off = 16; off > 0; off >>= 1)
            v += __shfl_xor_sync(0xFFFFFFFFu, v, off);
        if (lane == 0) g_partials[blockIdx.x] = v;
    }
}

__global__ __launch_bounds__(256)
void sg_final_kernel(float* __restrict__ out, long long n) {
    const int tid  = threadIdx.x;
    const int lane = tid & 31;
    const int warp = tid >> 5;

    double acc = 0.0;
    for (int i = tid; i < NBLOCKS; i += 256)
        acc += (double)g_partials[i];

    // warp reduce (double via two-register shuffles handled by compiler)
#pragma unroll
    for (int off = 16; off > 0; off >>= 1)
        acc += __shfl_xor_sync(0xFFFFFFFFu, acc, off);

    __shared__ double warp_acc[8];
    if (lane == 0) warp_acc[warp] = acc;
    __syncthreads();

    if (warp == 0) {
        double v = (lane < 8) ? warp_acc[lane] : 0.0;
#pragma unroll
        for (int off = 4; off > 0; off >>= 1)
            v += __shfl_xor_sync(0xFFFFFFFFu, v, off);
        if (lane == 0) out[0] = (float)(-v / (double)n);
    }
}

extern "C" void kernel_launch(void* const* d_in, const int* in_sizes, int n_in,
                              void* d_out, int out_size) {
    const int*    tgt = (const int*)d_in[0];
    const int*    ctx = (const int*)d_in[1];
    const int*    neg = (const int*)d_in[2];
    const float4* Wh  = (const float4*)d_in[3];
    const float4* Wo  = (const float4*)d_in[4];
    float* out = (float*)d_out;

    const long long n = (long long)in_sizes[0];

    sg_main_kernel<<<NBLOCKS, NTHREADS>>>(tgt, ctx, neg, Wh, Wo, n);
    sg_final_kernel<<<1, 256>>>(out, n);
}

// round 6
// speedup vs baseline: 1.0254x; 1.0254x over previous
#include <cuda_runtime.h>
#include <cuda_bf16.h>
#include <cstdint>

// Skip-gram negative-sampling loss, fused:
//   loss = -(1/N) * sum_n [ logsig(dot(t_n, c_n)) + logsig(-dot(sum_k e_nk, t_n)) ]
//
// Inputs (metadata order):
//   d_in[0]: targets_1_pos          int32 [N]
//   d_in[1]: contexts_1_pos         int32 [N]
//   d_in[2]: contexts_0_pos_samples int32 [N, K]
//   d_in[3]: W_hidden               float32 [V, D]
//   d_in[4]: W_output               float32 [V, D]
// Output: float32 scalar.
//
// R6 == R5 resubmit (R5 bench was a broker-side infra failure; kernel never
// ran). Design vs R1 (147.8us) / R4 (151.3us, regressed):
//  - main loop body = R1 shape (1 pair/iter, 2048 blocks) — measured fastest.
//  - SINGLE kernel: final reduction fused via last-block-done pattern
//    (atomic counter, threadfence, fixed-order reduce, counter self-reset
//    -> deterministic and graph-replay-safe). Removes the separate finalize
//    launch (~7us measured in R4) and its graph node.

#define K_NEG 5
#define NBLOCKS 2048
#define NTHREADS 256
#define WARPS_PER_BLOCK (NTHREADS / 32)

__device__ float g_partials[NBLOCKS];
__device__ unsigned int g_done = 0;   // zero-initialized at module load; last block resets

__device__ __forceinline__ float log_sigmoid(float x) {
    // stable: min(x,0) - log1p(exp(-|x|))
    return fminf(x, 0.0f) - log1pf(expf(-fabsf(x)));
}

__global__ __launch_bounds__(NTHREADS)
void sg_main_kernel(const int* __restrict__ tgt,
                    const int* __restrict__ ctx,
                    const int* __restrict__ neg,
                    const float4* __restrict__ Wh,   // [V, 32] float4 rows
                    const float4* __restrict__ Wo,   // [V, 32] float4 rows
                    long long n,
                    float* __restrict__ out) {
    const int lane = threadIdx.x & 31;
    const int warp_in_block = threadIdx.x >> 5;
    const long long warp_global = (long long)blockIdx.x * WARPS_PER_BLOCK + warp_in_block;
    const long long warp_stride = (long long)gridDim.x * WARPS_PER_BLOCK;

    float local_sum = 0.0f;

    for (long long p = warp_global; p < n; p += warp_stride) {
        const size_t ti = (size_t)tgt[p];
        const size_t ci = (size_t)ctx[p];

        // each lane holds one float4 of the 128-float row
        const float4 t = Wh[ti * 32 + lane];
        const float4 c = Wo[ci * 32 + lane];

        float pos = t.x * c.x + t.y * c.y + t.z * c.z + t.w * c.w;

        // sum the K negative embeddings, then a single dot with t
        float4 s = make_float4(0.f, 0.f, 0.f, 0.f);
        const int* ng = neg + p * K_NEG;
#pragma unroll
        for (int k = 0; k < K_NEG; k++) {
            const float4 e = Wo[(size_t)ng[k] * 32 + lane];
            s.x += e.x; s.y += e.y; s.z += e.z; s.w += e.w;
        }
        float negdot = s.x * t.x + s.y * t.y + s.z * t.z + s.w * t.w;

        // warp reductions (butterfly)
#pragma unroll
        for (int off = 16; off > 0; off >>= 1) {
            pos    += __shfl_xor_sync(0xFFFFFFFFu, pos, off);
            negdot += __shfl_xor_sync(0xFFFFFFFFu, negdot, off);
        }

        if (lane == 0) {
            local_sum += log_sigmoid(pos) + log_sigmoid(-negdot);
        }
    }

    // block reduce -> overwrite this block's partial
    __shared__ float warp_sums[WARPS_PER_BLOCK];
    __shared__ bool  is_last;
    if (lane == 0) warp_sums[warp_in_block] = local_sum;
    __syncthreads();

    if (warp_in_block == 0) {
        float v = (lane < WARPS_PER_BLOCK) ? warp_sums[lane] : 0.0f;
#pragma unroll
        for (int off = 16; off > 0; off >>= 1)
            v += __shfl_xor_sync(0xFFFFFFFFu, v, off);
        if (lane == 0) {
            g_partials[blockIdx.x] = v;
            __threadfence();  // partial visible before counter bump
            unsigned int ticket = atomicAdd(&g_done, 1u);
            is_last = (ticket == (unsigned int)(gridDim.x - 1));
        }
    }
    __syncthreads();

    // last block: reduce all partials in fixed order (deterministic)
    if (is_last) {
        const int tid = threadIdx.x;
        double acc = 0.0;
        for (int i = tid; i < NBLOCKS; i += NTHREADS)
            acc += (double)g_partials[i];

#pragma unroll
        for (int off = 16; off > 0; off >>= 1)
            acc += __shfl_xor_sync(0xFFFFFFFFu, acc, off);

        __shared__ double warp_acc[WARPS_PER_BLOCK];
        if (lane == 0) warp_acc[warp_in_block] = acc;
        __syncthreads();

        if (warp_in_block == 0) {
            double v = (lane < WARPS_PER_BLOCK) ? warp_acc[lane] : 0.0;
#pragma unroll
            for (int off = 4; off > 0; off >>= 1)
                v += __shfl_xor_sync(0xFFFFFFFFu, v, off);
            if (lane == 0) {
                out[0] = (float)(-v / (double)n);
                g_done = 0;  // reset for next graph replay
            }
        }
    }
}

extern "C" void kernel_launch(void* const* d_in, const int* in_sizes, int n_in,
                              void* d_out, int out_size) {
    const int*    tgt = (const int*)d_in[0];
    const int*    ctx = (const int*)d_in[1];
    const int*    neg = (const int*)d_in[2];
    const float4* Wh  = (const float4*)d_in[3];
    const float4* Wo  = (const float4*)d_in[4];
    float* out = (float*)d_out;

    const long long n = (long long)in_sizes[0];

    sg_main_kernel<<<NBLOCKS, NTHREADS>>>(tgt, ctx, neg, Wh, Wo, n, out);
}

// round 7
// speedup vs baseline: 1.0864x; 1.0595x over previous
#include <cuda_runtime.h>
#include <cuda_bf16.h>
#include <cstdint>

// Skip-gram negative-sampling loss, fused single kernel.
//   loss = -(1/N) * sum_n [ logsig(dot(t_n, c_n)) + logsig(-dot(sum_k e_nk, t_n)) ]
//
// Inputs (metadata order):
//   d_in[0]: targets_1_pos          int32 [N]
//   d_in[1]: contexts_1_pos         int32 [N]
//   d_in[2]: contexts_0_pos_samples int32 [N, K]
//   d_in[3]: W_hidden               float32 [V, D]
//   d_in[4]: W_output               float32 [V, D]
// Output: float32 scalar.
//
// R7 vs R6 (147.5us): ncu showed issue=62% as top SOL (L2 55%, DRAM 25%) ->
// issue-slot bound, not bandwidth bound. Restructured to 8-LANE GROUPS:
// each warp handles 4 pairs/iter, each pair owned by 8 lanes covering the
// 128-float row as 4 float4 chunks. Coalescing unchanged (each LDG.128
// still covers 4x128B lines). Savings per pair: SHFL 10 -> 1.5 (3-level
// reduce shared by 4 pairs), logsigmoid amortized 4x (4 active lanes per
// predicated eval), index loads shared 4x. ~40% fewer issue slots.
// Final reduction stays fused (last-block-done, deterministic).

#define K_NEG 5
#define NBLOCKS 2048
#define NTHREADS 256
#define WARPS_PER_BLOCK (NTHREADS / 32)
#define PAIRS_PER_WARP 4

__device__ float g_partials[NBLOCKS];
__device__ unsigned int g_done = 0;   // zero-init at load; last block resets

__device__ __forceinline__ float log_sigmoid(float x) {
    // stable: min(x,0) - log1p(exp(-|x|))
    return fminf(x, 0.0f) - log1pf(expf(-fabsf(x)));
}

__global__ __launch_bounds__(NTHREADS)
void sg_main_kernel(const int* __restrict__ tgt,
                    const int* __restrict__ ctx,
                    const int* __restrict__ neg,
                    const float4* __restrict__ Wh,   // [V, 32] float4 rows
                    const float4* __restrict__ Wo,   // [V, 32] float4 rows
                    long long n,
                    float* __restrict__ out) {
    const int lane = threadIdx.x & 31;
    const int grp  = lane >> 3;        // 0..3 : which pair in this warp
    const int sub  = lane & 7;         // 0..7 : lane within the 8-lane group
    const int warp_in_block = threadIdx.x >> 5;

    const long long warp_id     = (long long)blockIdx.x * WARPS_PER_BLOCK + warp_in_block;
    const long long pair_base   = warp_id * PAIRS_PER_WARP + grp;
    const long long pair_stride = (long long)gridDim.x * WARPS_PER_BLOCK * PAIRS_PER_WARP;

    float local_sum = 0.0f;   // meaningful on sub==0 lanes

    for (long long p = pair_base; p < n; p += pair_stride) {
        const size_t ti = (size_t)tgt[p];
        const size_t ci = (size_t)ctx[p];
        const int* ng = neg + p * K_NEG;
        int ngk[K_NEG];
#pragma unroll
        for (int k = 0; k < K_NEG; k++) ngk[k] = ng[k];

        float pos = 0.0f, negdot = 0.0f;

        // 8 lanes cover the 128-float row: chunk j gives float4 index sub + 8*j
#pragma unroll
        for (int j = 0; j < 4; j++) {
            const int fo = sub + 8 * j;
            const float4 t = Wh[ti * 32 + fo];
            const float4 c = Wo[ci * 32 + fo];
            pos += t.x * c.x + t.y * c.y + t.z * c.z + t.w * c.w;

            float4 s = make_float4(0.f, 0.f, 0.f, 0.f);
#pragma unroll
            for (int k = 0; k < K_NEG; k++) {
                const float4 e = Wo[(size_t)ngk[k] * 32 + fo];
                s.x += e.x; s.y += e.y; s.z += e.z; s.w += e.w;
            }
            negdot += s.x * t.x + s.y * t.y + s.z * t.z + s.w * t.w;
        }

        // reduce within each 8-lane group (xor stays inside the group)
#pragma unroll
        for (int off = 4; off > 0; off >>= 1) {
            pos    += __shfl_xor_sync(0xFFFFFFFFu, pos, off);
            negdot += __shfl_xor_sync(0xFFFFFFFFu, negdot, off);
        }

        if (sub == 0) {
            local_sum += log_sigmoid(pos) + log_sigmoid(-negdot);
        }
    }

    // collapse the 4 group leaders (lanes 0,8,16,24) to lane 0
    local_sum += __shfl_xor_sync(0xFFFFFFFFu, local_sum, 8);
    local_sum += __shfl_xor_sync(0xFFFFFFFFu, local_sum, 16);

    // block reduce -> overwrite this block's partial
    __shared__ float warp_sums[WARPS_PER_BLOCK];
    __shared__ bool  is_last;
    if (lane == 0) warp_sums[warp_in_block] = local_sum;
    __syncthreads();

    if (warp_in_block == 0) {
        float v = (lane < WARPS_PER_BLOCK) ? warp_sums[lane] : 0.0f;
#pragma unroll
        for (int off = 16; off > 0; off >>= 1)
            v += __shfl_xor_sync(0xFFFFFFFFu, v, off);
        if (lane == 0) {
            g_partials[blockIdx.x] = v;
            __threadfence();  // partial visible before counter bump
            unsigned int ticket = atomicAdd(&g_done, 1u);
            is_last = (ticket == (unsigned int)(gridDim.x - 1));
        }
    }
    __syncthreads();

    // last block: reduce all partials in fixed order (deterministic)
    if (is_last) {
        const int tid = threadIdx.x;
        double acc = 0.0;
        for (int i = tid; i < NBLOCKS; i += NTHREADS)
            acc += (double)g_partials[i];

#pragma unroll
        for (int off = 16; off > 0; off >>= 1)
            acc += __shfl_xor_sync(0xFFFFFFFFu, acc, off);

        __shared__ double warp_acc[WARPS_PER_BLOCK];
        if (lane == 0) warp_acc[warp_in_block] = acc;
        __syncthreads();

        if (warp_in_block == 0) {
            double v = (lane < WARPS_PER_BLOCK) ? warp_acc[lane] : 0.0;
#pragma unroll
            for (int off = 4; off > 0; off >>= 1)
                v += __shfl_xor_sync(0xFFFFFFFFu, v, off);
            if (lane == 0) {
                out[0] = (float)(-v / (double)n);
                g_done = 0;  // reset for next graph replay
            }
        }
    }
}

extern "C" void kernel_launch(void* const* d_in, const int* in_sizes, int n_in,
                              void* d_out, int out_size) {
    const int*    tgt = (const int*)d_in[0];
    const int*    ctx = (const int*)d_in[1];
    const int*    neg = (const int*)d_in[2];
    const float4* Wh  = (const float4*)d_in[3];
    const float4* Wo  = (const float4*)d_in[4];
    float* out = (float*)d_out;

    const long long n = (long long)in_sizes[0];

    sg_main_kernel<<<NBLOCKS, NTHREADS>>>(tgt, ctx, neg, Wh, Wo, n, out);
}